// round 3
// baseline (speedup 1.0000x reference)
#include <cuda_runtime.h>
#include <stdint.h>

typedef unsigned int u32;
typedef uint8_t u8;

// Ping-pong activation scratch: 16 imgs * 512*512 pixels * up to 16 ch (NHWC)
__device__ __align__(16) u8 g_bufA[(size_t)16 * 512 * 512 * 16];
__device__ __align__(16) u8 g_bufB[(size_t)16 * 512 * 512 * 16];

__device__ __forceinline__ int dp4a_us(u32 a, int b, int c) {
    int d;
    asm("dp4a.u32.s32 %0, %1, %2, %3;" : "=r"(d) : "r"(a), "r"(b), "r"(c));
    return d;
}
__device__ __forceinline__ int dp4a_ss(int a, int b, int c) {
    int d;
    asm("dp4a.s32.s32 %0, %1, %2, %3;" : "=r"(d) : "r"(a), "r"(b), "r"(c));
    return d;
}

// requantize: clip(round(acc*M), -127,127) then relu  ==  clamp(round, 0, 127)
__device__ __forceinline__ u32 requant(int acc, float M) {
    int iv = __float2int_rn((float)acc * M);
    iv = min(iv, 127);
    iv = max(iv, 0);
    return (u32)iv;
}

// ---------------------------------------------------------------------------
// Quantize input: a0 = clip(rint(x / (1/255)), 0, 255)  -> g_bufB (1 B/pixel)
// ---------------------------------------------------------------------------
__global__ __launch_bounds__(256) void k_quant(const float* __restrict__ x) {
    int i = blockIdx.x * 256 + threadIdx.x;   // uint4-granule index
    const float inv_s = (float)(1.0 / 255.0);
    float4 v = ((const float4*)x)[i];
    u32 b0 = (u32)min(max(__float2int_rn(v.x / inv_s), 0), 255);
    u32 b1 = (u32)min(max(__float2int_rn(v.y / inv_s), 0), 255);
    u32 b2 = (u32)min(max(__float2int_rn(v.z / inv_s), 0), 255);
    u32 b3 = (u32)min(max(__float2int_rn(v.w / inv_s), 0), 255);
    ((u32*)g_bufB)[i] = b0 | (b1 << 8) | (b2 << 16) | (b3 << 24);
}

// ---------------------------------------------------------------------------
// Layer 0: 5x5 conv, 1 -> 16 ch, pad 2.  in: g_bufB (u8), out: g_bufA NHWC16
// ---------------------------------------------------------------------------
__global__ __launch_bounds__(256) void k_l0(const int* __restrict__ w0,
                                            const int* __restrict__ b0, float M0) {
    __shared__ __align__(16) u8 tile[12][36];
    __shared__ __align__(16) int4 sw[16][2];
    int tx = threadIdx.x, ty = threadIdx.y;
    int tid = ty * 32 + tx;
    int bx = blockIdx.x * 32, by = blockIdx.y * 8, n = blockIdx.z;
    size_t ibase = (size_t)n * 262144;

    // input tile with halo 2 (zero pad)
    for (int i = tid; i < 432; i += 256) {
        int r = i / 36, c = i % 36;
        int gy = by - 2 + r, gx = bx - 2 + c;
        u8 v = 0;
        if ((unsigned)gy < 512u && (unsigned)gx < 512u)
            v = g_bufB[ibase + (size_t)gy * 512 + gx];
        tile[r][c] = v;
    }
    // weight packing: per oc: row words (kx0..3) for ky0..4, column word (kx=4,ky0..3),
    // corner (4,4), bias
    if (tid < 16) {
        int oc = tid;
        int rw[5];
        int cw = 0;
#pragma unroll
        for (int ky = 0; ky < 5; ky++) {
            int wv = 0;
#pragma unroll
            for (int kx = 0; kx < 4; kx++)
                wv |= ((w0[oc * 25 + ky * 5 + kx] - 128) & 255) << (8 * kx);
            rw[ky] = wv;
        }
#pragma unroll
        for (int ky = 0; ky < 4; ky++)
            cw |= ((w0[oc * 25 + ky * 5 + 4] - 128) & 255) << (8 * ky);
        int corner = w0[oc * 25 + 24] - 128;
        sw[oc][0] = make_int4(rw[0], rw[1], rw[2], rw[3]);
        sw[oc][1] = make_int4(rw[4], cw, corner, b0[oc]);
    }
    __syncthreads();

    // gather 5x5 activation window as packed words
    u32 r[5], colw = 0;
    int corner_v = 0;
    int s = (tx & 3) * 8;
#pragma unroll
    for (int k = 0; k < 5; k++) {
        const u32* rowp = (const u32*)&tile[ty + k][0];
        u32 wlo = rowp[tx >> 2], whi = rowp[(tx >> 2) + 1];
        r[k] = __funnelshift_r(wlo, whi, s);   // bytes tx..tx+3
        u32 b4 = (whi >> s) & 255u;            // byte tx+4
        if (k < 4) colw |= b4 << (8 * k); else corner_v = (int)b4;
    }

    u32 ow[4] = {0, 0, 0, 0};
#pragma unroll
    for (int oc = 0; oc < 16; oc++) {
        int4 qa = sw[oc][0];
        int4 qb = sw[oc][1];
        int acc = qb.w;
        acc = dp4a_us(r[0], qa.x, acc);
        acc = dp4a_us(r[1], qa.y, acc);
        acc = dp4a_us(r[2], qa.z, acc);
        acc = dp4a_us(r[3], qa.w, acc);
        acc = dp4a_us(r[4], qb.x, acc);
        acc = dp4a_us(colw, qb.y, acc);
        acc += corner_v * qb.z;
        ow[oc >> 2] |= requant(acc, M0) << ((oc & 3) * 8);
    }
    size_t p = ibase + (size_t)(by + ty) * 512 + (bx + tx);
    ((uint4*)g_bufA)[p] = make_uint4(ow[0], ow[1], ow[2], ow[3]);
}

// ---------------------------------------------------------------------------
// Layer 1: 1x1 conv, 16 -> 12.  in: g_bufA NHWC16, out: g_bufB NHWC12
// ---------------------------------------------------------------------------
__global__ __launch_bounds__(256) void k_l1(const int* __restrict__ w,
                                            const int* __restrict__ b, float M) {
    __shared__ int4 sw[12];
    __shared__ int sb[12];
    int tid = threadIdx.x;
    if (tid < 12) {
        int oc = tid;
        int ww[4];
#pragma unroll
        for (int g = 0; g < 4; g++) {
            int v = 0;
#pragma unroll
            for (int j = 0; j < 4; j++)
                v |= ((w[oc * 16 + 4 * g + j] - 128) & 255) << (8 * j);
            ww[g] = v;
        }
        sw[oc] = make_int4(ww[0], ww[1], ww[2], ww[3]);
        sb[oc] = b[oc];
    }
    __syncthreads();
    size_t p = (size_t)blockIdx.x * 256 + tid;
    uint4 a = ((const uint4*)g_bufA)[p];
    u32 ow[3] = {0, 0, 0};
#pragma unroll
    for (int oc = 0; oc < 12; oc++) {
        int4 q = sw[oc];
        int acc = sb[oc];
        acc = dp4a_ss((int)a.x, q.x, acc);
        acc = dp4a_ss((int)a.y, q.y, acc);
        acc = dp4a_ss((int)a.z, q.z, acc);
        acc = dp4a_ss((int)a.w, q.w, acc);
        ow[oc >> 2] |= requant(acc, M) << ((oc & 3) * 8);
    }
    u32* op = (u32*)g_bufB + p * 3;
    op[0] = ow[0]; op[1] = ow[1]; op[2] = ow[2];
}

// ---------------------------------------------------------------------------
// Layers 2-5: 3x3 conv, 12 -> 12, pad 1.  dir=0: B->A, dir=1: A->B
// ---------------------------------------------------------------------------
__global__ __launch_bounds__(256) void k_l3(int dir, const int* __restrict__ w,
                                            const int* __restrict__ b, float M) {
    const u8* in = dir ? g_bufA : g_bufB;
    u8* out = dir ? g_bufB : g_bufA;
    __shared__ __align__(16) u32 stile[1020];   // 34 x 10 pixels x 3 words
    __shared__ __align__(16) int sww[12 * 28];  // per-oc 27 packed words + pad
    __shared__ int sb[12];
    int tx = threadIdx.x, ty = threadIdx.y;
    int tid = ty * 32 + tx;
    int bx = blockIdx.x * 32, by = blockIdx.y * 8, n = blockIdx.z;
    size_t ibase = (size_t)n * 262144;

    for (int i = tid; i < 12 * 28; i += 256) {
        int oc = i / 28, t = i % 28;
        int word = 0;
        if (t < 27) {
            int tap = t / 3, g = t % 3;
            int ky = tap / 3, kx = tap % 3;
#pragma unroll
            for (int j = 0; j < 4; j++) {
                int ic = g * 4 + j;
                word |= ((w[((oc * 12 + ic) * 3 + ky) * 3 + kx] - 128) & 255) << (8 * j);
            }
        }
        sww[i] = word;
    }
    if (tid < 12) sb[tid] = b[tid];
    for (int i = tid; i < 1020; i += 256) {
        int pix = i / 3, g = i % 3;
        int row = pix / 34, col = pix % 34;
        int gy = by - 1 + row, gx = bx - 1 + col;
        u32 v = 0;
        if ((unsigned)gy < 512u && (unsigned)gx < 512u)
            v = ((const u32*)in)[(ibase + (size_t)gy * 512 + gx) * 3 + g];
        stile[i] = v;
    }
    __syncthreads();

    int v[27];
#pragma unroll
    for (int ky = 0; ky < 3; ky++)
#pragma unroll
        for (int kx = 0; kx < 3; kx++)
#pragma unroll
            for (int g = 0; g < 3; g++)
                v[(ky * 3 + kx) * 3 + g] =
                    (int)stile[((ty + ky) * 34 + (tx + kx)) * 3 + g];

    u32 ow[3] = {0, 0, 0};
#pragma unroll
    for (int oc = 0; oc < 12; oc++) {
        alignas(16) int wr[28];
#pragma unroll
        for (int k = 0; k < 7; k++)
            ((int4*)wr)[k] = ((const int4*)(sww + oc * 28))[k];
        int acc = sb[oc];
#pragma unroll
        for (int k = 0; k < 27; k++) acc = dp4a_ss(v[k], wr[k], acc);
        ow[oc >> 2] |= requant(acc, M) << ((oc & 3) * 8);
    }
    size_t p = ibase + (size_t)(by + ty) * 512 + (bx + tx);
    u32* op = (u32*)out + p * 3;
    op[0] = ow[0]; op[1] = ow[1]; op[2] = ow[2];
}

// ---------------------------------------------------------------------------
// Layer 6: 1x1 conv, 12 -> 16.  in: g_bufB NHWC12, out: g_bufA NHWC16
// ---------------------------------------------------------------------------
__global__ __launch_bounds__(256) void k_l6(const int* __restrict__ w,
                                            const int* __restrict__ b, float M) {
    __shared__ int sw[16][3];
    __shared__ int sb[16];
    int tid = threadIdx.x;
    if (tid < 16) {
        int oc = tid;
#pragma unroll
        for (int g = 0; g < 3; g++) {
            int v = 0;
#pragma unroll
            for (int j = 0; j < 4; j++)
                v |= ((w[oc * 12 + 4 * g + j] - 128) & 255) << (8 * j);
            sw[oc][g] = v;
        }
        sb[oc] = b[oc];
    }
    __syncthreads();
    size_t p = (size_t)blockIdx.x * 256 + tid;
    const u32* ip = (const u32*)g_bufB + p * 3;
    int a0 = (int)ip[0], a1 = (int)ip[1], a2 = (int)ip[2];
    u32 ow[4] = {0, 0, 0, 0};
#pragma unroll
    for (int oc = 0; oc < 16; oc++) {
        int acc = sb[oc];
        acc = dp4a_ss(a0, sw[oc][0], acc);
        acc = dp4a_ss(a1, sw[oc][1], acc);
        acc = dp4a_ss(a2, sw[oc][2], acc);
        ow[oc >> 2] |= requant(acc, M) << ((oc & 3) * 8);
    }
    ((uint4*)g_bufA)[p] = make_uint4(ow[0], ow[1], ow[2], ow[3]);
}

// ---------------------------------------------------------------------------
// Transpose conv: stride 4, k 9, pad 4.  in: g_bufA NHWC16 (*0.05), out float
// Each thread computes one 4x4 output cell.  out[oy] uses in[iy=t+1-j] with
// kernel index ky = ry + 4*jy (jy=2 only valid for ry=0).
// ---------------------------------------------------------------------------
__global__ __launch_bounds__(256) void k_deconv(const float* __restrict__ wt,
                                                float* __restrict__ out) {
    __shared__ __align__(16) uint4 tile[340];      // 34 x 10 pixels, 16 ch
    __shared__ __align__(16) float ws[81 * 16];    // [tap][ch], *0.05 folded
    int tx = threadIdx.x, ty = threadIdx.y;
    int tid = ty * 32 + tx;
    int bx = blockIdx.x * 32, by = blockIdx.y * 8, n = blockIdx.z;
    size_t ibase = (size_t)n * 262144;

    for (int i = tid; i < 1296; i += 256) {
        int c = i / 81, t = i % 81;
        ws[t * 16 + c] = wt[c * 81 + t] * 0.05f;
    }
    for (int i = tid; i < 340; i += 256) {
        int r = i / 34, cc = i % 34;
        int py = by - 1 + r, px = bx - 1 + cc;
        uint4 vv = make_uint4(0, 0, 0, 0);
        if ((unsigned)py < 512u && (unsigned)px < 512u)
            vv = ((const uint4*)g_bufA)[ibase + (size_t)py * 512 + px];
        tile[i] = vv;
    }
    __syncthreads();

    float acc[16];
#pragma unroll
    for (int k = 0; k < 16; k++) acc[k] = 0.0f;

#pragma unroll
    for (int jy = 0; jy < 3; jy++) {
#pragma unroll
        for (int jx = 0; jx < 3; jx++) {
            uint4 pw = tile[(ty + 2 - jy) * 34 + (tx + 2 - jx)];
            u32 wds[4] = {pw.x, pw.y, pw.z, pw.w};
            float v[16];
#pragma unroll
            for (int k = 0; k < 16; k++)
                v[k] = (float)(int)((wds[k >> 2] >> ((k & 3) * 8)) & 255u);
            const int rycnt = (jy == 2) ? 1 : 4;
            const int rxcnt = (jx == 2) ? 1 : 4;
#pragma unroll
            for (int ry = 0; ry < rycnt; ry++) {
#pragma unroll
                for (int rx = 0; rx < rxcnt; rx++) {
                    const float* wp = &ws[((ry + 4 * jy) * 9 + (rx + 4 * jx)) * 16];
                    float a = acc[ry * 4 + rx];
#pragma unroll
                    for (int c = 0; c < 16; c++) a += v[c] * wp[c];
                    acc[ry * 4 + rx] = a;
                }
            }
        }
    }

    int oy0 = (by + ty) * 4, ox0 = (bx + tx) * 4;
    size_t obase = (size_t)n * 2045 * 2045;
#pragma unroll
    for (int ry = 0; ry < 4; ry++) {
        int oy = oy0 + ry;
        if (oy >= 2045) continue;
#pragma unroll
        for (int rx = 0; rx < 4; rx++) {
            int ox = ox0 + rx;
            if (ox < 2045)
                out[obase + (size_t)oy * 2045 + ox] = acc[ry * 4 + rx];
        }
    }
}

// ---------------------------------------------------------------------------
extern "C" void kernel_launch(void* const* d_in, const int* in_sizes, int n_in,
                              void* d_out, int out_size) {
    const float* x = (const float*)d_in[0];
    const int* w[7];
    const int* b[7];
    // Input ordering: interleaved (x,w0,b0,w1,b1,...) if d_in[2] has 16 elems
    // (b0); grouped (x,w0..w6,b0..b6,wt) if d_in[2] has 192 elems (w1).
    if (in_sizes[2] == 16) {
        for (int i = 0; i < 7; i++) {
            w[i] = (const int*)d_in[1 + 2 * i];
            b[i] = (const int*)d_in[2 + 2 * i];
        }
    } else {
        for (int i = 0; i < 7; i++) {
            w[i] = (const int*)d_in[1 + i];
            b[i] = (const int*)d_in[8 + i];
        }
    }
    const float* wt = (const float*)d_in[15];

    // Requant scales computed exactly as JAX: double expr -> f32
    float M0 = (float)((1.0 / 255.0) * 0.02 / 0.05);
    float M1 = (float)(0.05 * 0.02 / 0.04);
    float M2 = (float)(0.04 * 0.02 / 0.04);
    float M6 = (float)(0.04 * 0.02 / 0.05);

    dim3 blk(32, 8), grd(16, 64, 16);
    k_quant<<<4096, 256>>>(x);
    k_l0<<<grd, blk>>>(w[0], b[0], M0);
    k_l1<<<16384, 256>>>(w[1], b[1], M1);
    k_l3<<<grd, blk>>>(0, w[2], b[2], M2);   // B -> A
    k_l3<<<grd, blk>>>(1, w[3], b[3], M2);   // A -> B
    k_l3<<<grd, blk>>>(0, w[4], b[4], M2);   // B -> A
    k_l3<<<grd, blk>>>(1, w[5], b[5], M2);   // A -> B
    k_l6<<<16384, 256>>>(w[6], b[6], M6);    // B -> A
    k_deconv<<<grd, blk>>>(wt, (float*)d_out);
}

// round 4
// speedup vs baseline: 1.0914x; 1.0914x over previous
#include <cuda_runtime.h>
#include <stdint.h>

typedef unsigned int u32;
typedef uint8_t u8;

// Ping-pong activation scratch: 16 imgs * 512*512 pixels * up to 16 ch (NHWC)
__device__ __align__(16) u8 g_bufA[(size_t)16 * 512 * 512 * 16];
__device__ __align__(16) u8 g_bufB[(size_t)16 * 512 * 512 * 16];

__device__ __forceinline__ int dp4a_us(u32 a, int b, int c) {
    int d;
    asm("dp4a.u32.s32 %0, %1, %2, %3;" : "=r"(d) : "r"(a), "r"(b), "r"(c));
    return d;
}
__device__ __forceinline__ int dp4a_ss(int a, int b, int c) {
    int d;
    asm("dp4a.s32.s32 %0, %1, %2, %3;" : "=r"(d) : "r"(a), "r"(b), "r"(c));
    return d;
}

// requantize: clip(round(acc*M), -127,127) then relu  ==  clamp(round, 0, 127)
__device__ __forceinline__ u32 requant(int acc, float M) {
    int iv = __float2int_rn((float)acc * M);
    iv = min(iv, 127);
    iv = max(iv, 0);
    return (u32)iv;
}

// ---------------------------------------------------------------------------
// Quantize input: a0 = clip(rint(x / (1/255)), 0, 255)  -> g_bufB (1 B/pixel)
// ---------------------------------------------------------------------------
__global__ __launch_bounds__(256) void k_quant(const float* __restrict__ x) {
    int i = blockIdx.x * 256 + threadIdx.x;   // uint4-granule index
    const float inv_s = (float)(1.0 / 255.0);
    float4 v = ((const float4*)x)[i];
    u32 b0 = (u32)min(max(__float2int_rn(v.x / inv_s), 0), 255);
    u32 b1 = (u32)min(max(__float2int_rn(v.y / inv_s), 0), 255);
    u32 b2 = (u32)min(max(__float2int_rn(v.z / inv_s), 0), 255);
    u32 b3 = (u32)min(max(__float2int_rn(v.w / inv_s), 0), 255);
    ((u32*)g_bufB)[i] = b0 | (b1 << 8) | (b2 << 16) | (b3 << 24);
}

// ---------------------------------------------------------------------------
// Layer 0: 5x5 conv, 1 -> 16 ch, pad 2.  in: g_bufB (u8), out: g_bufA NHWC16
// ---------------------------------------------------------------------------
__global__ __launch_bounds__(256) void k_l0(const int* __restrict__ w0,
                                            const int* __restrict__ b0, float M0) {
    __shared__ __align__(16) u8 tile[12][36];
    __shared__ __align__(16) int4 sw[16][2];
    int tx = threadIdx.x, ty = threadIdx.y;
    int tid = ty * 32 + tx;
    int bx = blockIdx.x * 32, by = blockIdx.y * 8, n = blockIdx.z;
    size_t ibase = (size_t)n * 262144;

    for (int i = tid; i < 432; i += 256) {
        int r = i / 36, c = i % 36;
        int gy = by - 2 + r, gx = bx - 2 + c;
        u8 v = 0;
        if ((unsigned)gy < 512u && (unsigned)gx < 512u)
            v = g_bufB[ibase + (size_t)gy * 512 + gx];
        tile[r][c] = v;
    }
    if (tid < 16) {
        int oc = tid;
        int rw[5];
        int cw = 0;
#pragma unroll
        for (int ky = 0; ky < 5; ky++) {
            int wv = 0;
#pragma unroll
            for (int kx = 0; kx < 4; kx++)
                wv |= ((w0[oc * 25 + ky * 5 + kx] - 128) & 255) << (8 * kx);
            rw[ky] = wv;
        }
#pragma unroll
        for (int ky = 0; ky < 4; ky++)
            cw |= ((w0[oc * 25 + ky * 5 + 4] - 128) & 255) << (8 * ky);
        int corner = w0[oc * 25 + 24] - 128;
        sw[oc][0] = make_int4(rw[0], rw[1], rw[2], rw[3]);
        sw[oc][1] = make_int4(rw[4], cw, corner, b0[oc]);
    }
    __syncthreads();

    u32 r[5], colw = 0;
    int corner_v = 0;
    int s = (tx & 3) * 8;
#pragma unroll
    for (int k = 0; k < 5; k++) {
        const u32* rowp = (const u32*)&tile[ty + k][0];
        u32 wlo = rowp[tx >> 2], whi = rowp[(tx >> 2) + 1];
        r[k] = __funnelshift_r(wlo, whi, s);
        u32 b4 = (whi >> s) & 255u;
        if (k < 4) colw |= b4 << (8 * k); else corner_v = (int)b4;
    }

    u32 ow[4] = {0, 0, 0, 0};
#pragma unroll
    for (int oc = 0; oc < 16; oc++) {
        int4 qa = sw[oc][0];
        int4 qb = sw[oc][1];
        int acc = qb.w;
        acc = dp4a_us(r[0], qa.x, acc);
        acc = dp4a_us(r[1], qa.y, acc);
        acc = dp4a_us(r[2], qa.z, acc);
        acc = dp4a_us(r[3], qa.w, acc);
        acc = dp4a_us(r[4], qb.x, acc);
        acc = dp4a_us(colw, qb.y, acc);
        acc += corner_v * qb.z;
        ow[oc >> 2] |= requant(acc, M0) << ((oc & 3) * 8);
    }
    size_t p = ibase + (size_t)(by + ty) * 512 + (bx + tx);
    ((uint4*)g_bufA)[p] = make_uint4(ow[0], ow[1], ow[2], ow[3]);
}

// ---------------------------------------------------------------------------
// Layer 1: 1x1 conv, 16 -> 12.  in: g_bufA NHWC16, out: g_bufB NHWC12
// ---------------------------------------------------------------------------
__global__ __launch_bounds__(256) void k_l1(const int* __restrict__ w,
                                            const int* __restrict__ b, float M) {
    __shared__ int4 sw[12];
    __shared__ int sb[12];
    int tid = threadIdx.x;
    if (tid < 12) {
        int oc = tid;
        int ww[4];
#pragma unroll
        for (int g = 0; g < 4; g++) {
            int v = 0;
#pragma unroll
            for (int j = 0; j < 4; j++)
                v |= ((w[oc * 16 + 4 * g + j] - 128) & 255) << (8 * j);
            ww[g] = v;
        }
        sw[oc] = make_int4(ww[0], ww[1], ww[2], ww[3]);
        sb[oc] = b[oc];
    }
    __syncthreads();
    size_t p = (size_t)blockIdx.x * 256 + tid;
    uint4 a = ((const uint4*)g_bufA)[p];
    u32 ow[3] = {0, 0, 0};
#pragma unroll
    for (int oc = 0; oc < 12; oc++) {
        int4 q = sw[oc];
        int acc = sb[oc];
        acc = dp4a_ss((int)a.x, q.x, acc);
        acc = dp4a_ss((int)a.y, q.y, acc);
        acc = dp4a_ss((int)a.z, q.z, acc);
        acc = dp4a_ss((int)a.w, q.w, acc);
        ow[oc >> 2] |= requant(acc, M) << ((oc & 3) * 8);
    }
    u32* op = (u32*)g_bufB + p * 3;
    op[0] = ow[0]; op[1] = ow[1]; op[2] = ow[2];
}

// ---------------------------------------------------------------------------
// Layers 2-5: 3x3 conv, 12 -> 12, pad 1.  dir=0: B->A, dir=1: A->B
// 4 pixels per thread along x. Tile 128x8 outputs, halo 130x10.
// SMEM activation layout: 3 planes [grp][row][col], 1 u32 (4ch) per pixel,
// row stride 132 so 4*tx u32 offset is 16B-aligned for vector LDS.
// ---------------------------------------------------------------------------
__global__ __launch_bounds__(256) void k_l3(int dir, const int* __restrict__ w,
                                            const int* __restrict__ b, float M) {
    const u8* in = dir ? g_bufA : g_bufB;
    u8* out = dir ? g_bufB : g_bufA;
    __shared__ __align__(16) u32 splane[3 * 10 * 132];   // 15840 B
    __shared__ __align__(16) int sww[12 * 28];           // packed weights
    __shared__ int sb[12];
    int tx = threadIdx.x, ty = threadIdx.y;
    int tid = ty * 32 + tx;
    int bx0 = blockIdx.x * 128, by = blockIdx.y * 8, n = blockIdx.z;
    size_t ibase = (size_t)n * 262144;

    // weights: per oc, 27 words (tap-major, 3 ic-groups each) + bias pad
    for (int i = tid; i < 12 * 28; i += 256) {
        int oc = i / 28, t = i % 28;
        int word = 0;
        if (t < 27) {
            int tap = t / 3, g = t % 3;
            int ky = tap / 3, kx = tap % 3;
#pragma unroll
            for (int j = 0; j < 4; j++) {
                int ic = g * 4 + j;
                word |= ((w[((oc * 12 + ic) * 3 + ky) * 3 + kx] - 128) & 255) << (8 * j);
            }
        }
        sww[i] = word;
    }
    if (tid < 12) sb[tid] = b[tid];

    // activation tile: 3 planes x 10 rows x 130 cols (stride 132)
    for (int i = tid; i < 3900; i += 256) {
        int g = i / 1300, rem = i % 1300;
        int row = rem / 130, col = rem % 130;
        int gy = by - 1 + row, gx = bx0 - 1 + col;
        u32 v = 0;
        if ((unsigned)gy < 512u && (unsigned)gx < 512u)
            v = ((const u32*)in)[(ibase + (size_t)gy * 512 + gx) * 3 + g];
        splane[(g * 10 + row) * 132 + col] = v;
    }
    __syncthreads();

    // Register activation window: rows ty..ty+2, cols 4tx..4tx+5 (6), 3 groups
    int av[3][3][6];
#pragma unroll
    for (int r = 0; r < 3; r++) {
#pragma unroll
        for (int g = 0; g < 3; g++) {
            const uint4* pp = (const uint4*)&splane[((g * 10) + ty + r) * 132 + 4 * tx];
            uint4 lo = pp[0], hi = pp[1];
            av[r][g][0] = (int)lo.x; av[r][g][1] = (int)lo.y;
            av[r][g][2] = (int)lo.z; av[r][g][3] = (int)lo.w;
            av[r][g][4] = (int)hi.x; av[r][g][5] = (int)hi.y;
        }
    }

    u32 owf[12];
#pragma unroll
    for (int i = 0; i < 12; i++) owf[i] = 0;

#pragma unroll
    for (int oc = 0; oc < 12; oc++) {
        alignas(16) int wr[28];
#pragma unroll
        for (int q = 0; q < 7; q++)
            ((int4*)wr)[q] = ((const int4*)(sww + oc * 28))[q];
        int bias = sb[oc];
        int acc0 = bias, acc1 = bias, acc2 = bias, acc3 = bias;
#pragma unroll
        for (int ky = 0; ky < 3; ky++) {
#pragma unroll
            for (int kx = 0; kx < 3; kx++) {
#pragma unroll
                for (int g = 0; g < 3; g++) {
                    int wv = wr[(ky * 3 + kx) * 3 + g];
                    acc0 = dp4a_ss(av[ky][g][kx + 0], wv, acc0);
                    acc1 = dp4a_ss(av[ky][g][kx + 1], wv, acc1);
                    acc2 = dp4a_ss(av[ky][g][kx + 2], wv, acc2);
                    acc3 = dp4a_ss(av[ky][g][kx + 3], wv, acc3);
                }
            }
        }
        int gsel = oc >> 2, sh = (oc & 3) * 8;
        owf[0 * 3 + gsel] |= requant(acc0, M) << sh;
        owf[1 * 3 + gsel] |= requant(acc1, M) << sh;
        owf[2 * 3 + gsel] |= requant(acc2, M) << sh;
        owf[3 * 3 + gsel] |= requant(acc3, M) << sh;
    }

    // 4 pixels * 12B = 48B contiguous, 16B-aligned -> 3 STG.128
    size_t p0 = ibase + (size_t)(by + ty) * 512 + (bx0 + 4 * tx);
    uint4* op = (uint4*)((u32*)out + p0 * 3);
    op[0] = make_uint4(owf[0], owf[1], owf[2], owf[3]);
    op[1] = make_uint4(owf[4], owf[5], owf[6], owf[7]);
    op[2] = make_uint4(owf[8], owf[9], owf[10], owf[11]);
}

// ---------------------------------------------------------------------------
// Layer 6: 1x1 conv, 12 -> 16.  in: g_bufB NHWC12, out: g_bufA NHWC16
// ---------------------------------------------------------------------------
__global__ __launch_bounds__(256) void k_l6(const int* __restrict__ w,
                                            const int* __restrict__ b, float M) {
    __shared__ int sw[16][3];
    __shared__ int sb[16];
    int tid = threadIdx.x;
    if (tid < 16) {
        int oc = tid;
#pragma unroll
        for (int g = 0; g < 3; g++) {
            int v = 0;
#pragma unroll
            for (int j = 0; j < 4; j++)
                v |= ((w[oc * 12 + 4 * g + j] - 128) & 255) << (8 * j);
            sw[oc][g] = v;
        }
        sb[oc] = b[oc];
    }
    __syncthreads();
    size_t p = (size_t)blockIdx.x * 256 + tid;
    const u32* ip = (const u32*)g_bufB + p * 3;
    int a0 = (int)ip[0], a1 = (int)ip[1], a2 = (int)ip[2];
    u32 ow[4] = {0, 0, 0, 0};
#pragma unroll
    for (int oc = 0; oc < 16; oc++) {
        int acc = sb[oc];
        acc = dp4a_ss(a0, sw[oc][0], acc);
        acc = dp4a_ss(a1, sw[oc][1], acc);
        acc = dp4a_ss(a2, sw[oc][2], acc);
        ow[oc >> 2] |= requant(acc, M) << ((oc & 3) * 8);
    }
    ((uint4*)g_bufA)[p] = make_uint4(ow[0], ow[1], ow[2], ow[3]);
}

// ---------------------------------------------------------------------------
// Transpose conv: stride 4, k 9, pad 4.  in: g_bufA NHWC16 (*0.05), out float
// 2 input pixels per thread -> 8x4 outputs. Weight LDS amortized 2x; input
// bytes unpacked to float via rolling 2-column buffer (each column once).
// ---------------------------------------------------------------------------
__global__ __launch_bounds__(256) void k_deconv(const float* __restrict__ wt,
                                                float* __restrict__ out) {
    __shared__ __align__(16) uint4 tile[10 * 66];   // rows 10, cols 66, 16 ch
    __shared__ __align__(16) float ws[81 * 16];     // [tap][ch], *0.05 folded
    int tx = threadIdx.x, ty = threadIdx.y;
    int tid = ty * 32 + tx;
    int bx0 = blockIdx.x * 64, by = blockIdx.y * 8, n = blockIdx.z;
    size_t ibase = (size_t)n * 262144;

    for (int i = tid; i < 1296; i += 256) {
        int c = i / 81, t = i % 81;
        ws[t * 16 + c] = wt[c * 81 + t] * 0.05f;
    }
    for (int i = tid; i < 660; i += 256) {
        int r = i / 66, cc = i % 66;
        int py = by - 1 + r, px = bx0 - 1 + cc;
        uint4 vv = make_uint4(0, 0, 0, 0);
        if ((unsigned)py < 512u && (unsigned)px < 512u)
            vv = ((const uint4*)g_bufA)[ibase + (size_t)py * 512 + px];
        tile[i] = vv;
    }
    __syncthreads();

    float accA[16], accB[16];
#pragma unroll
    for (int k = 0; k < 16; k++) { accA[k] = 0.0f; accB[k] = 0.0f; }

    int p0 = 2 * tx;   // tile-local col of pixel A; pixel B = p0+1

#pragma unroll
    for (int jy = 0; jy < 3; jy++) {
        int rowb = (ty + 2 - jy) * 66 + p0;
        float fb[2][16];
        // unpack helper (col offset off in 0..3 relative to p0)
#define UNPACK(dst, off)                                                    \
        {                                                                   \
            uint4 pw = tile[rowb + (off)];                                  \
            u32 wd[4] = {pw.x, pw.y, pw.z, pw.w};                           \
            _Pragma("unroll")                                               \
            for (int c = 0; c < 16; c++)                                    \
                dst[c] = (float)(int)((wd[c >> 2] >> ((c & 3) * 8)) & 255u);\
        }
        UNPACK(fb[0], 2)   // col p0+2
        UNPACK(fb[1], 3)   // col p0+3
        const int rycnt = (jy == 2) ? 1 : 4;
#pragma unroll
        for (int jx = 0; jx < 3; jx++) {
            // pixel A window col = p0+2-jx ; pixel B window col = p0+3-jx
            // parity: (p0+2-jx)&1 = jx&1 ; (p0+3-jx)&1 = (jx+1)&1
            const float* fA = fb[jx & 1];
            const float* fB = fb[(jx + 1) & 1];
            const int rxcnt = (jx == 2) ? 1 : 4;
#pragma unroll
            for (int ry = 0; ry < 4; ry++) {
                if (ry >= rycnt) break;
#pragma unroll
                for (int rx = 0; rx < 4; rx++) {
                    if (rx >= rxcnt) break;
                    const float4* wp = (const float4*)&ws[((ry + 4 * jy) * 9 + (rx + 4 * jx)) * 16];
                    float4 w0 = wp[0], w1 = wp[1], w2 = wp[2], w3 = wp[3];
                    float a = accA[ry * 4 + rx];
                    float bb = accB[ry * 4 + rx];
                    a += fA[0] * w0.x;  bb += fB[0] * w0.x;
                    a += fA[1] * w0.y;  bb += fB[1] * w0.y;
                    a += fA[2] * w0.z;  bb += fB[2] * w0.z;
                    a += fA[3] * w0.w;  bb += fB[3] * w0.w;
                    a += fA[4] * w1.x;  bb += fB[4] * w1.x;
                    a += fA[5] * w1.y;  bb += fB[5] * w1.y;
                    a += fA[6] * w1.z;  bb += fB[6] * w1.z;
                    a += fA[7] * w1.w;  bb += fB[7] * w1.w;
                    a += fA[8] * w2.x;  bb += fB[8] * w2.x;
                    a += fA[9] * w2.y;  bb += fB[9] * w2.y;
                    a += fA[10] * w2.z; bb += fB[10] * w2.z;
                    a += fA[11] * w2.w; bb += fB[11] * w2.w;
                    a += fA[12] * w3.x; bb += fB[12] * w3.x;
                    a += fA[13] * w3.y; bb += fB[13] * w3.y;
                    a += fA[14] * w3.z; bb += fB[14] * w3.z;
                    a += fA[15] * w3.w; bb += fB[15] * w3.w;
                    accA[ry * 4 + rx] = a;
                    accB[ry * 4 + rx] = bb;
                }
            }
            // roll buffer: next jx needs col p0+1-jx at parity (jx&1)
            if (jx == 0) UNPACK(fb[1], 1)        // col p0+1 (parity 1)
            else if (jx == 1) UNPACK(fb[0], 0)   // col p0   (parity 0)
        }
#undef UNPACK
    }

    int X0 = bx0 + p0;          // global input pixel of A
    int oy0 = (by + ty) * 4;
    size_t obase = (size_t)n * 2045 * 2045;
#pragma unroll
    for (int ry = 0; ry < 4; ry++) {
        int oy = oy0 + ry;
        if (oy >= 2045) continue;
        size_t rbase = obase + (size_t)oy * 2045;
#pragma unroll
        for (int rx = 0; rx < 4; rx++) {
            int oxA = 4 * X0 + rx;
            int oxB = oxA + 4;
            if (oxA < 2045) out[rbase + oxA] = accA[ry * 4 + rx];
            if (oxB < 2045) out[rbase + oxB] = accB[ry * 4 + rx];
        }
    }
}

// ---------------------------------------------------------------------------
extern "C" void kernel_launch(void* const* d_in, const int* in_sizes, int n_in,
                              void* d_out, int out_size) {
    const float* x = (const float*)d_in[0];
    const int* w[7];
    const int* b[7];
    if (in_sizes[2] == 16) {
        for (int i = 0; i < 7; i++) {
            w[i] = (const int*)d_in[1 + 2 * i];
            b[i] = (const int*)d_in[2 + 2 * i];
        }
    } else {
        for (int i = 0; i < 7; i++) {
            w[i] = (const int*)d_in[1 + i];
            b[i] = (const int*)d_in[8 + i];
        }
    }
    const float* wt = (const float*)d_in[15];

    float M0 = (float)((1.0 / 255.0) * 0.02 / 0.05);
    float M1 = (float)(0.05 * 0.02 / 0.04);
    float M2 = (float)(0.04 * 0.02 / 0.04);
    float M6 = (float)(0.04 * 0.02 / 0.05);

    dim3 blk(32, 8);
    dim3 grd0(16, 64, 16);     // 1 px/thread kernels (l0)
    dim3 grd3(4, 64, 16);      // k_l3: 128x8 tile
    dim3 grdD(8, 64, 16);      // deconv: 64x8 input tile
    k_quant<<<4096, 256>>>(x);
    k_l0<<<grd0, blk>>>(w[0], b[0], M0);
    k_l1<<<16384, 256>>>(w[1], b[1], M1);
    k_l3<<<grd3, blk>>>(0, w[2], b[2], M2);   // B -> A
    k_l3<<<grd3, blk>>>(1, w[3], b[3], M2);   // A -> B
    k_l3<<<grd3, blk>>>(0, w[4], b[4], M2);   // B -> A
    k_l3<<<grd3, blk>>>(1, w[5], b[5], M2);   // A -> B
    k_l6<<<16384, 256>>>(w[6], b[6], M6);     // B -> A
    k_deconv<<<grdD, blk>>>(wt, (float*)d_out);
}

// round 5
// speedup vs baseline: 1.1871x; 1.0877x over previous
#include <cuda_runtime.h>
#include <stdint.h>

typedef unsigned int u32;
typedef unsigned long long u64;
typedef uint8_t u8;

// Ping-pong activation scratch: 16 imgs * 512*512 pixels * up to 16 ch (NHWC)
__device__ __align__(16) u8 g_bufA[(size_t)16 * 512 * 512 * 16];
__device__ __align__(16) u8 g_bufB[(size_t)16 * 512 * 512 * 16];

__device__ __forceinline__ int dp4a_us(u32 a, int b, int c) {
    int d;
    asm("dp4a.u32.s32 %0, %1, %2, %3;" : "=r"(d) : "r"(a), "r"(b), "r"(c));
    return d;
}
__device__ __forceinline__ int dp4a_ss(int a, int b, int c) {
    int d;
    asm("dp4a.s32.s32 %0, %1, %2, %3;" : "=r"(d) : "r"(a), "r"(b), "r"(c));
    return d;
}
__device__ __forceinline__ u64 fma2(u64 a, u64 b, u64 c) {
    u64 d;
    asm("fma.rn.f32x2 %0, %1, %2, %3;" : "=l"(d) : "l"(a), "l"(b), "l"(c));
    return d;
}
__device__ __forceinline__ u64 pack2(float lo, float hi) {
    u64 d;
    asm("mov.b64 %0, {%1, %2};" : "=l"(d) : "f"(lo), "f"(hi));
    return d;
}

// requantize: clip(round(acc*M), -127,127) then relu  ==  clamp(round, 0, 127)
__device__ __forceinline__ u32 requant(int acc, float M) {
    int iv = __float2int_rn((float)acc * M);
    iv = min(iv, 127);
    iv = max(iv, 0);
    return (u32)iv;
}

// ---------------------------------------------------------------------------
// Front: quantize + layer0 (5x5, 1->16, pad 2) + layer1 (1x1, 16->12) fused.
// in: x float, out: g_bufB NHWC12
// ---------------------------------------------------------------------------
__global__ __launch_bounds__(256) void k_front(const float* __restrict__ x,
                                               const int* __restrict__ w0,
                                               const int* __restrict__ b0,
                                               const int* __restrict__ w1,
                                               const int* __restrict__ b1,
                                               float M0, float M1) {
    __shared__ __align__(16) u8 tile[12][36];
    __shared__ __align__(16) int4 sw[16][2];
    __shared__ int4 sw1[12];
    __shared__ int sb1[12];
    int tx = threadIdx.x, ty = threadIdx.y;
    int tid = ty * 32 + tx;
    int bx = blockIdx.x * 32, by = blockIdx.y * 8, n = blockIdx.z;
    size_t ibase = (size_t)n * 262144;
    const float inv_s = (float)(1.0 / 255.0);

    // quantize input tile with halo 2 (zero pad)
    for (int i = tid; i < 432; i += 256) {
        int r = i / 36, c = i % 36;
        int gy = by - 2 + r, gx = bx - 2 + c;
        u8 v = 0;
        if ((unsigned)gy < 512u && (unsigned)gx < 512u) {
            float f = x[ibase + (size_t)gy * 512 + gx];
            v = (u8)min(max(__float2int_rn(f / inv_s), 0), 255);
        }
        tile[r][c] = v;
    }
    if (tid < 16) {
        int oc = tid;
        int rw[5];
        int cw = 0;
#pragma unroll
        for (int ky = 0; ky < 5; ky++) {
            int wv = 0;
#pragma unroll
            for (int kx = 0; kx < 4; kx++)
                wv |= ((w0[oc * 25 + ky * 5 + kx] - 128) & 255) << (8 * kx);
            rw[ky] = wv;
        }
#pragma unroll
        for (int ky = 0; ky < 4; ky++)
            cw |= ((w0[oc * 25 + ky * 5 + 4] - 128) & 255) << (8 * ky);
        int corner = w0[oc * 25 + 24] - 128;
        sw[oc][0] = make_int4(rw[0], rw[1], rw[2], rw[3]);
        sw[oc][1] = make_int4(rw[4], cw, corner, b0[oc]);
    }
    if (tid >= 32 && tid < 44) {
        int oc = tid - 32;
        int ww[4];
#pragma unroll
        for (int g = 0; g < 4; g++) {
            int v = 0;
#pragma unroll
            for (int j = 0; j < 4; j++)
                v |= ((w1[oc * 16 + 4 * g + j] - 128) & 255) << (8 * j);
            ww[g] = v;
        }
        sw1[oc] = make_int4(ww[0], ww[1], ww[2], ww[3]);
        sb1[oc] = b1[oc];
    }
    __syncthreads();

    // layer0 per pixel
    u32 r[5], colw = 0;
    int corner_v = 0;
    int s = (tx & 3) * 8;
#pragma unroll
    for (int k = 0; k < 5; k++) {
        const u32* rowp = (const u32*)&tile[ty + k][0];
        u32 wlo = rowp[tx >> 2], whi = rowp[(tx >> 2) + 1];
        r[k] = __funnelshift_r(wlo, whi, s);
        u32 b4 = (whi >> s) & 255u;
        if (k < 4) colw |= b4 << (8 * k); else corner_v = (int)b4;
    }

    u32 a16[4] = {0, 0, 0, 0};
#pragma unroll
    for (int oc = 0; oc < 16; oc++) {
        int4 qa = sw[oc][0];
        int4 qb = sw[oc][1];
        int acc = qb.w;
        acc = dp4a_us(r[0], qa.x, acc);
        acc = dp4a_us(r[1], qa.y, acc);
        acc = dp4a_us(r[2], qa.z, acc);
        acc = dp4a_us(r[3], qa.w, acc);
        acc = dp4a_us(r[4], qb.x, acc);
        acc = dp4a_us(colw, qb.y, acc);
        acc += corner_v * qb.z;
        a16[oc >> 2] |= requant(acc, M0) << ((oc & 3) * 8);
    }

    // layer1 (1x1, 16->12) in registers
    u32 ow[3] = {0, 0, 0};
#pragma unroll
    for (int oc = 0; oc < 12; oc++) {
        int4 q = sw1[oc];
        int acc = sb1[oc];
        acc = dp4a_ss((int)a16[0], q.x, acc);
        acc = dp4a_ss((int)a16[1], q.y, acc);
        acc = dp4a_ss((int)a16[2], q.z, acc);
        acc = dp4a_ss((int)a16[3], q.w, acc);
        ow[oc >> 2] |= requant(acc, M1) << ((oc & 3) * 8);
    }
    size_t p = ibase + (size_t)(by + ty) * 512 + (bx + tx);
    u32* op = (u32*)g_bufB + p * 3;
    op[0] = ow[0]; op[1] = ow[1]; op[2] = ow[2];
}

// ---------------------------------------------------------------------------
// Layers 2-5: 3x3 conv, 12 -> 12, pad 1.  dir=0: B->A, dir=1: A->B
// 4 pixels per thread; weights streamed per-ky; outputs stored per oc-group.
// ---------------------------------------------------------------------------
__global__ __launch_bounds__(256, 3) void k_l3(int dir, const int* __restrict__ w,
                                               const int* __restrict__ b, float M) {
    const u8* in = dir ? g_bufA : g_bufB;
    u8* out = dir ? g_bufB : g_bufA;
    __shared__ __align__(16) u32 splane[3 * 10 * 132];   // 15840 B
    __shared__ __align__(16) int sww[12 * 40];           // [oc][ky][12]+bias@36
    int tx = threadIdx.x, ty = threadIdx.y;
    int tid = ty * 32 + tx;
    int bx0 = blockIdx.x * 128, by = blockIdx.y * 8, n = blockIdx.z;
    size_t ibase = (size_t)n * 262144;

    // weights: word idx = oc*40 + ky*12 + kx*3 + g ; bias at oc*40+36
    for (int i = tid; i < 12 * 40; i += 256) {
        int oc = i / 40, t = i % 40;
        int word = 0;
        if (t < 36) {
            int ky = t / 12, j = t % 12;
            if (j < 9) {
                int kx = j / 3, g = j % 3;
#pragma unroll
                for (int jj = 0; jj < 4; jj++) {
                    int ic = g * 4 + jj;
                    word |= ((w[((oc * 12 + ic) * 3 + ky) * 3 + kx] - 128) & 255) << (8 * jj);
                }
            }
        } else if (t == 36) {
            word = b[oc];
        }
        sww[i] = word;
    }

    // activation tile: 3 planes x 10 rows x 130 cols (stride 132)
    for (int i = tid; i < 3900; i += 256) {
        int g = i / 1300, rem = i % 1300;
        int row = rem / 130, col = rem % 130;
        int gy = by - 1 + row, gx = bx0 - 1 + col;
        u32 v = 0;
        if ((unsigned)gy < 512u && (unsigned)gx < 512u)
            v = ((const u32*)in)[(ibase + (size_t)gy * 512 + gx) * 3 + g];
        splane[(g * 10 + row) * 132 + col] = v;
    }
    __syncthreads();

    // Register activation window: rows ty..ty+2, cols 4tx..4tx+5 (6), 3 groups
    int av[3][3][6];
#pragma unroll
    for (int r = 0; r < 3; r++) {
#pragma unroll
        for (int g = 0; g < 3; g++) {
            const uint4* pp = (const uint4*)&splane[((g * 10) + ty + r) * 132 + 4 * tx];
            uint4 lo = pp[0], hi = pp[1];
            av[r][g][0] = (int)lo.x; av[r][g][1] = (int)lo.y;
            av[r][g][2] = (int)lo.z; av[r][g][3] = (int)lo.w;
            av[r][g][4] = (int)hi.x; av[r][g][5] = (int)hi.y;
        }
    }

    size_t p0 = ibase + (size_t)(by + ty) * 512 + (bx0 + 4 * tx);
    u32* ob = (u32*)out + p0 * 3;

    u32 go0 = 0, go1 = 0, go2 = 0, go3 = 0;
#pragma unroll
    for (int oc = 0; oc < 12; oc++) {
        int bias = sww[oc * 40 + 36];
        int acc0 = bias, acc1 = bias, acc2 = bias, acc3 = bias;
#pragma unroll
        for (int ky = 0; ky < 3; ky++) {
            alignas(16) int wv[12];
            const int4* wp = (const int4*)&sww[oc * 40 + ky * 12];
            ((int4*)wv)[0] = wp[0];
            ((int4*)wv)[1] = wp[1];
            ((int4*)wv)[2] = wp[2];
#pragma unroll
            for (int kx = 0; kx < 3; kx++) {
#pragma unroll
                for (int g = 0; g < 3; g++) {
                    int wvx = wv[kx * 3 + g];
                    acc0 = dp4a_ss(av[ky][g][kx + 0], wvx, acc0);
                    acc1 = dp4a_ss(av[ky][g][kx + 1], wvx, acc1);
                    acc2 = dp4a_ss(av[ky][g][kx + 2], wvx, acc2);
                    acc3 = dp4a_ss(av[ky][g][kx + 3], wvx, acc3);
                }
            }
        }
        int sh = (oc & 3) * 8;
        go0 |= requant(acc0, M) << sh;
        go1 |= requant(acc1, M) << sh;
        go2 |= requant(acc2, M) << sh;
        go3 |= requant(acc3, M) << sh;
        if ((oc & 3) == 3) {
            int gsel = oc >> 2;
            ob[0 * 3 + gsel] = go0;
            ob[1 * 3 + gsel] = go1;
            ob[2 * 3 + gsel] = go2;
            ob[3 * 3 + gsel] = go3;
            go0 = go1 = go2 = go3 = 0;
        }
    }
}

// ---------------------------------------------------------------------------
// Deconv fused with layer6 (1x1, 12->16).  in: g_bufB NHWC12, out: float.
// l6 applied during halo-tile fill; main loop uses packed fma.rn.f32x2
// (8 f32x2 per tap-cell instead of 16 FFMA).
// ---------------------------------------------------------------------------
__global__ __launch_bounds__(256) void k_deconv(const int* __restrict__ w6,
                                                const int* __restrict__ b6, float M6,
                                                const float* __restrict__ wt,
                                                float* __restrict__ out) {
    __shared__ __align__(16) uint4 tile[340];      // 34 x 10 pixels, 16 ch
    __shared__ __align__(16) float ws[81 * 16];    // [tap][ch], *0.05 folded
    __shared__ int sw6[16][3];
    __shared__ int sb6[16];
    int tx = threadIdx.x, ty = threadIdx.y;
    int tid = ty * 32 + tx;
    int bx = blockIdx.x * 32, by = blockIdx.y * 8, n = blockIdx.z;
    size_t ibase = (size_t)n * 262144;

    if (tid < 16) {
        int oc = tid;
#pragma unroll
        for (int g = 0; g < 3; g++) {
            int v = 0;
#pragma unroll
            for (int j = 0; j < 4; j++)
                v |= ((w6[oc * 12 + 4 * g + j] - 128) & 255) << (8 * j);
            sw6[oc][g] = v;
        }
        sb6[oc] = b6[oc];
    }
    for (int i = tid; i < 1296; i += 256) {
        int c = i / 81, t = i % 81;
        ws[t * 16 + c] = wt[c * 81 + t] * 0.05f;
    }
    __syncthreads();

    // tile fill with fused l6
    for (int i = tid; i < 340; i += 256) {
        int r = i / 34, cc = i % 34;
        int py = by - 1 + r, px = bx - 1 + cc;
        uint4 vv = make_uint4(0, 0, 0, 0);
        if ((unsigned)py < 512u && (unsigned)px < 512u) {
            const u32* ip = (const u32*)g_bufB + (ibase + (size_t)py * 512 + px) * 3;
            int a0 = (int)ip[0], a1 = (int)ip[1], a2 = (int)ip[2];
            u32 o[4] = {0, 0, 0, 0};
#pragma unroll
            for (int oc = 0; oc < 16; oc++) {
                int acc = sb6[oc];
                acc = dp4a_ss(a0, sw6[oc][0], acc);
                acc = dp4a_ss(a1, sw6[oc][1], acc);
                acc = dp4a_ss(a2, sw6[oc][2], acc);
                o[oc >> 2] |= requant(acc, M6) << ((oc & 3) * 8);
            }
            vv = make_uint4(o[0], o[1], o[2], o[3]);
        }
        tile[i] = vv;
    }
    __syncthreads();

    u64 acc2[16];
#pragma unroll
    for (int k = 0; k < 16; k++) acc2[k] = 0ull;

#pragma unroll
    for (int jy = 0; jy < 3; jy++) {
#pragma unroll
        for (int jx = 0; jx < 3; jx++) {
            uint4 pw = tile[(ty + 2 - jy) * 34 + (tx + 2 - jx)];
            u32 wd[4] = {pw.x, pw.y, pw.z, pw.w};
            u64 v2[8];
#pragma unroll
            for (int q = 0; q < 4; q++) {
                float f0 = (float)(int)(wd[q] & 255u);
                float f1 = (float)(int)((wd[q] >> 8) & 255u);
                float f2 = (float)(int)((wd[q] >> 16) & 255u);
                float f3 = (float)(int)((wd[q] >> 24) & 255u);
                v2[q * 2 + 0] = pack2(f0, f1);
                v2[q * 2 + 1] = pack2(f2, f3);
            }
            const int rycnt = (jy == 2) ? 1 : 4;
            const int rxcnt = (jx == 2) ? 1 : 4;
#pragma unroll
            for (int ry = 0; ry < 4; ry++) {
                if (ry >= rycnt) break;
#pragma unroll
                for (int rx = 0; rx < 4; rx++) {
                    if (rx >= rxcnt) break;
                    const ulonglong2* wp =
                        (const ulonglong2*)&ws[((ry + 4 * jy) * 9 + (rx + 4 * jx)) * 16];
                    ulonglong2 wa = wp[0], wb = wp[1], wc = wp[2], wdd = wp[3];
                    u64 a = acc2[ry * 4 + rx];
                    a = fma2(v2[0], wa.x, a);
                    a = fma2(v2[1], wa.y, a);
                    a = fma2(v2[2], wb.x, a);
                    a = fma2(v2[3], wb.y, a);
                    a = fma2(v2[4], wc.x, a);
                    a = fma2(v2[5], wc.y, a);
                    a = fma2(v2[6], wdd.x, a);
                    a = fma2(v2[7], wdd.y, a);
                    acc2[ry * 4 + rx] = a;
                }
            }
        }
    }

    int oy0 = (by + ty) * 4, ox0 = (bx + tx) * 4;
    size_t obase = (size_t)n * 2045 * 2045;
#pragma unroll
    for (int ry = 0; ry < 4; ry++) {
        int oy = oy0 + ry;
        if (oy >= 2045) continue;
        size_t rbase = obase + (size_t)oy * 2045;
#pragma unroll
        for (int rx = 0; rx < 4; rx++) {
            int ox = ox0 + rx;
            if (ox < 2045) {
                float2 pr = *(float2*)&acc2[ry * 4 + rx];
                out[rbase + ox] = pr.x + pr.y;
            }
        }
    }
}

// ---------------------------------------------------------------------------
extern "C" void kernel_launch(void* const* d_in, const int* in_sizes, int n_in,
                              void* d_out, int out_size) {
    const float* x = (const float*)d_in[0];
    const int* w[7];
    const int* b[7];
    if (in_sizes[2] == 16) {
        for (int i = 0; i < 7; i++) {
            w[i] = (const int*)d_in[1 + 2 * i];
            b[i] = (const int*)d_in[2 + 2 * i];
        }
    } else {
        for (int i = 0; i < 7; i++) {
            w[i] = (const int*)d_in[1 + i];
            b[i] = (const int*)d_in[8 + i];
        }
    }
    const float* wt = (const float*)d_in[15];

    float M0 = (float)((1.0 / 255.0) * 0.02 / 0.05);
    float M1 = (float)(0.05 * 0.02 / 0.04);
    float M2 = (float)(0.04 * 0.02 / 0.04);
    float M6 = (float)(0.04 * 0.02 / 0.05);

    dim3 blk(32, 8);
    dim3 grdF(16, 64, 16);     // front: 32x8 tiles
    dim3 grd3(4, 64, 16);      // k_l3: 128x8 tiles
    dim3 grdD(16, 64, 16);     // deconv: 32x8 input tiles
    k_front<<<grdF, blk>>>(x, w[0], b[0], w[1], b[1], M0, M1);
    k_l3<<<grd3, blk>>>(0, w[2], b[2], M2);   // B -> A
    k_l3<<<grd3, blk>>>(1, w[3], b[3], M2);   // A -> B
    k_l3<<<grd3, blk>>>(0, w[4], b[4], M2);   // B -> A
    k_l3<<<grd3, blk>>>(1, w[5], b[5], M2);   // A -> B
    k_deconv<<<grdD, blk>>>(w[6], b[6], M6, wt, (float*)d_out);
}